// round 9
// baseline (speedup 1.0000x reference)
#include <cuda_runtime.h>
#include <cuda_fp16.h>
#include <cstdint>
#include <math.h>

// Fused kernel, block tile 128x128, 8 warps.
// A: fp16 hi+lo (exact fp32 split), B: fp16 hi only.
//   dot = ah.bh + al.bh = a.bh   (err ~1e-4 rel, budget 1e-3)
// Epilogue staged through smem for fully dense STG.128.
#define STRIDE_A 80        // bytes; 80r mod 128 conflict-free
#define STRIDE_B 48
#define SM_A0 0            // 128*80 = 10240
#define SM_A1 10240
#define SM_B0 20480        // 128*48 = 6144
#define SM_B1 26624
#define STAGE_OFF 32768    // stage: 128 rows x 68 floats (64 used + 4 pad)
#define STAGE_STRIDE 68
#define SM_TOT (32768 + 128 * STAGE_STRIDE * 4)   // 67584

__device__ __forceinline__ uint32_t smem_u32(const void* p) {
    uint32_t a;
    asm("{ .reg .u64 t; cvta.to.shared.u64 t, %1; cvt.u32.u64 %0, t; }" : "=r"(a) : "l"(p));
    return a;
}
__device__ __forceinline__ void ldm_x4(uint32_t* r, uint32_t addr) {
    asm volatile("ldmatrix.sync.aligned.m8n8.x4.shared.b16 {%0,%1,%2,%3}, [%4];"
                 : "=r"(r[0]), "=r"(r[1]), "=r"(r[2]), "=r"(r[3]) : "r"(addr));
}
__device__ __forceinline__ void mma16816(float* d, const uint32_t* a,
                                         uint32_t b0, uint32_t b1) {
    asm volatile(
        "mma.sync.aligned.m16n8k16.row.col.f32.f16.f16.f32 "
        "{%0,%1,%2,%3}, {%4,%5,%6,%7}, {%8,%9}, {%0,%1,%2,%3};"
        : "+f"(d[0]), "+f"(d[1]), "+f"(d[2]), "+f"(d[3])
        : "r"(a[0]), "r"(a[1]), "r"(a[2]), "r"(a[3]), "r"(b0), "r"(b1));
}

__global__ void __launch_bounds__(256, 2)
qk_fused(const float* __restrict__ x, const float* __restrict__ c,
         float* __restrict__ out, int C) {
    extern __shared__ __align__(16) unsigned char sm[];
    const int tid = threadIdx.x, wid = tid >> 5, lane = tid & 31;
    const int row0 = blockIdx.y * 128, col0 = blockIdx.x * 128;
    const uint32_t sb = smem_u32(sm);

    // ---- Fused feature prologue: tid<128 -> A row, tid>=128 -> B col ----
    {
        const int r = tid & 127;
        const bool isB = tid >= 128;
        const float* src = isB ? (c + (size_t)(col0 + r) * 8)
                               : (x + (size_t)(row0 + r) * 8);
        float cv[8], sv[8];
        #pragma unroll
        for (int j = 0; j < 8; j++) sincosf(0.5f * src[j], &sv[j], &cv[j]);

        float pf[4][4];
        #pragma unroll
        for (int p = 0; p < 4; p++) {
            pf[p][0] = cv[2*p] * cv[2*p+1];
            pf[p][1] = cv[2*p] * sv[2*p+1];
            pf[p][2] = sv[2*p] * cv[2*p+1];
            pf[p][3] = sv[2*p] * sv[2*p+1];
        }
        #pragma unroll
        for (int g = 0; g < 2; g++) {
            if (!isB) {
                __align__(16) __half v[32];   // hi[16] | lo[16]
                #pragma unroll
                for (int a = 0; a < 4; a++)
                    #pragma unroll
                    for (int b = 0; b < 4; b++) {
                        float f = pf[2*g][a] * pf[2*g+1][b];
                        __half hi = __float2half_rn(f);
                        v[a*4+b]      = hi;
                        v[16 + a*4+b] = __float2half_rn(f - __half2float(hi));
                    }
                uint4* dst = (uint4*)(sm + (g ? SM_A1 : SM_A0) + r * STRIDE_A);
                #pragma unroll
                for (int j = 0; j < 4; j++) dst[j] = ((const uint4*)v)[j];
            } else {
                __align__(16) __half v[16];   // hi only
                #pragma unroll
                for (int a = 0; a < 4; a++)
                    #pragma unroll
                    for (int b = 0; b < 4; b++)
                        v[a*4+b] = __float2half_rn(pf[2*g][a] * pf[2*g+1][b]);
                uint4* dst = (uint4*)(sm + (g ? SM_B1 : SM_B0) + r * STRIDE_B);
                dst[0] = ((const uint4*)v)[0];
                dst[1] = ((const uint4*)v)[1];
            }
        }
    }
    __syncthreads();

    // ---- MMA mainloop: warp tile 32 rows x 64 cols ----
    const int wr = wid & 3;        // 4 row groups of 32
    const int wc = wid >> 2;       // 2 col groups of 64

    // Persistent a-frags: af[g][mt][hl][4], 32 regs.
    uint32_t af[2][2][2][4];
    {
        const uint32_t aoff =
            (uint32_t)(wr * 32 + (lane & 15)) * STRIDE_A + (lane >> 4) * 16;
        #pragma unroll
        for (int mt = 0; mt < 2; mt++)
            #pragma unroll
            for (int hl = 0; hl < 2; hl++) {
                ldm_x4(af[0][mt][hl], sb + SM_A0 + aoff + mt * 16 * STRIDE_A + hl * 32);
                ldm_x4(af[1][mt][hl], sb + SM_A1 + aoff + mt * 16 * STRIDE_A + hl * 32);
            }
    }

    // B ldmatrix base: one x4 covers an nt-pair (16 cols), hi only.
    const uint32_t boff =
        (uint32_t)(wc * 64 + (lane & 7) + ((lane >> 4) << 3)) * STRIDE_B +
        ((lane >> 3) & 1) * 16;
    const uint32_t bAddr0 = sb + SM_B0 + boff;
    const uint32_t bAddr1 = sb + SM_B1 + boff;

    float* stg = (float*)(sm + STAGE_OFF);
    const int rloc = wr * 32 + (lane >> 2);         // local row (mt adds 16)
    const int scol0 = wc * 32 + (lane & 3) * 2;     // staging col base

    #pragma unroll
    for (int pp = 0; pp < 2; pp++) {       // np pairs
        #pragma unroll
        for (int npl = 0; npl < 2; npl++) {
            const int np = pp * 2 + npl;
            const uint32_t bo = np * 16 * STRIDE_B;

            uint32_t b0[4], b1[4];
            ldm_x4(b0, bAddr0 + bo);
            ldm_x4(b1, bAddr1 + bo);

            float acc[2][2][2][4] = {};    // [g][mt][nt][4]

            #pragma unroll
            for (int mt = 0; mt < 2; mt++)
                #pragma unroll
                for (int nt = 0; nt < 2; nt++) {
                    mma16816(acc[0][mt][nt], af[0][mt][0], b0[2*nt], b0[2*nt+1]);
                    mma16816(acc[1][mt][nt], af[1][mt][0], b1[2*nt], b1[2*nt+1]);
                }
            #pragma unroll
            for (int mt = 0; mt < 2; mt++)
                #pragma unroll
                for (int nt = 0; nt < 2; nt++) {
                    mma16816(acc[0][mt][nt], af[0][mt][1], b0[2*nt], b0[2*nt+1]);
                    mma16816(acc[1][mt][nt], af[1][mt][1], b1[2*nt], b1[2*nt+1]);
                }

            // Product + scatter into staging (STS.64, conflict-free).
            #pragma unroll
            for (int mt = 0; mt < 2; mt++)
                #pragma unroll
                for (int nt = 0; nt < 2; nt++) {
                    int r = rloc + mt * 16;
                    int sc = scol0 + npl * 16 + nt * 8;
                    float2 v;
                    v.x = fabsf(acc[0][mt][nt][0] * acc[1][mt][nt][0]);
                    v.y = fabsf(acc[0][mt][nt][1] * acc[1][mt][nt][1]);
                    *(float2*)&stg[r * STAGE_STRIDE + sc] = v;
                    v.x = fabsf(acc[0][mt][nt][2] * acc[1][mt][nt][2]);
                    v.y = fabsf(acc[0][mt][nt][3] * acc[1][mt][nt][3]);
                    *(float2*)&stg[(r + 8) * STAGE_STRIDE + sc] = v;
                }
        }
        __syncthreads();

        // Drain: fully dense, 8 consecutive lanes -> one 128B run.
        #pragma unroll
        for (int k = 0; k < 8; k++) {
            int idx = tid + k * 256;
            int row = idx >> 4, sc4 = idx & 15;
            int wcd = sc4 >> 3, w8 = sc4 & 7;
            float4 v = *(const float4*)&stg[row * STAGE_STRIDE + wcd * 32 + w8 * 4];
            int gcol = col0 + wcd * 64 + pp * 32 + w8 * 4;
            *(float4*)(out + (size_t)(row0 + row) * C + gcol) = v;
        }
        __syncthreads();
    }
}

extern "C" void kernel_launch(void* const* d_in, const int* in_sizes, int n_in,
                              void* d_out, int out_size) {
    const float* x = (const float*)d_in[0];
    const float* c = (const float*)d_in[1];
    float* out = (float*)d_out;

    int B = in_sizes[0] / 8;   // 8192
    int C = in_sizes[1] / 8;   // 2048

    static int configured = 0;
    if (!configured) {
        cudaFuncSetAttribute(qk_fused, cudaFuncAttributeMaxDynamicSharedMemorySize, SM_TOT);
        configured = 1;
    }

    dim3 grid(C / 128, B / 128);
    qk_fused<<<grid, 256, SM_TOT>>>(x, c, out, C);
}

// round 10
// speedup vs baseline: 1.0821x; 1.0821x over previous
#include <cuda_runtime.h>
#include <cuda_fp16.h>
#include <cstdint>
#include <math.h>

// Split-engine fused kernel. Block tile 128 rows x 128 cols, 8 warps.
//   warps 0-3: HMMA on rows [0,64)   (fp16 hi/lo A x fp16-hi B, err ~1e-4)
//   warps 4-7: FFMA on rows [64,128) (fp32 rank-4 dot algebra, err ~2e-7)
// Both latency-bound paths overlap on disjoint pipes (tensor vs fma).
#define SM_AH 0          // HMMA A: 2 groups x 64 rows x 80B   = 10240
#define SM_BH 10240      // HMMA B: 2 groups x 128 cols x 48B  = 12288
#define SM_AF 22528      // FFMA A: 4 grp x 64 rows x 2 float4 =  8192
#define SM_BF 30720      // FFMA B: 4 grp x 2 fg x 64 pc float4=  8192
#define SM_TOT 38912

__device__ __forceinline__ uint32_t smem_u32(const void* p) {
    uint32_t a;
    asm("{ .reg .u64 t; cvta.to.shared.u64 t, %1; cvt.u32.u64 %0, t; }" : "=r"(a) : "l"(p));
    return a;
}
__device__ __forceinline__ void ldm_x4(uint32_t* r, uint32_t addr) {
    asm volatile("ldmatrix.sync.aligned.m8n8.x4.shared.b16 {%0,%1,%2,%3}, [%4];"
                 : "=r"(r[0]), "=r"(r[1]), "=r"(r[2]), "=r"(r[3]) : "r"(addr));
}
__device__ __forceinline__ void mma16816(float* d, const uint32_t* a,
                                         uint32_t b0, uint32_t b1) {
    asm volatile(
        "mma.sync.aligned.m16n8k16.row.col.f32.f16.f16.f32 "
        "{%0,%1,%2,%3}, {%4,%5,%6,%7}, {%8,%9}, {%0,%1,%2,%3};"
        : "+f"(d[0]), "+f"(d[1]), "+f"(d[2]), "+f"(d[3])
        : "r"(a[0]), "r"(a[1]), "r"(a[2]), "r"(a[3]), "r"(b0), "r"(b1));
}
union F4U { float4 f; unsigned long long u[2]; };

__global__ void __launch_bounds__(256, 2)
qk_split(const float* __restrict__ x, const float* __restrict__ c,
         float* __restrict__ out, int C) {
    extern __shared__ __align__(16) unsigned char sm[];
    const int tid = threadIdx.x, wid = tid >> 5, lane = tid & 31;
    const int row0 = blockIdx.y * 128, col0 = blockIdx.x * 128;
    const uint32_t sb = smem_u32(sm);

    // ---------------- Prologue: features in both formats ----------------
    {
        const bool isB = tid >= 128;
        const int r = tid & 127;
        const float* src = isB ? (c + (size_t)(col0 + r) * 8)
                               : (x + (size_t)(row0 + r) * 8);
        float cv[8], sv[8];
        #pragma unroll
        for (int j = 0; j < 8; j++) sincosf(0.5f * src[j], &sv[j], &cv[j]);
        float pf[4][4];
        #pragma unroll
        for (int p = 0; p < 4; p++) {
            pf[p][0] = cv[2*p] * cv[2*p+1];
            pf[p][1] = cv[2*p] * sv[2*p+1];
            pf[p][2] = sv[2*p] * cv[2*p+1];
            pf[p][3] = sv[2*p] * sv[2*p+1];
        }
        if (!isB && tid < 64) {
            // HMMA A rows 0-63: fp16 hi|lo, stride 80.
            #pragma unroll
            for (int g = 0; g < 2; g++) {
                __align__(16) __half v[32];
                #pragma unroll
                for (int a = 0; a < 4; a++)
                    #pragma unroll
                    for (int b = 0; b < 4; b++) {
                        float f = pf[2*g][a] * pf[2*g+1][b];
                        __half hi = __float2half_rn(f);
                        v[a*4+b]      = hi;
                        v[16 + a*4+b] = __float2half_rn(f - __half2float(hi));
                    }
                uint4* dst = (uint4*)(sm + SM_AH + g * 5120 + tid * 80);
                #pragma unroll
                for (int j = 0; j < 4; j++) dst[j] = ((const uint4*)v)[j];
            }
        } else if (!isB) {
            // FFMA A rows 64-127: duplicated fp32 float4 pairs.
            const int rl = tid - 64;
            float4* dst = (float4*)(sm + SM_AF);
            #pragma unroll
            for (int p = 0; p < 4; p++) {
                dst[(p * 64 + rl) * 2 + 0] =
                    make_float4(pf[p][0], pf[p][0], pf[p][1], pf[p][1]);
                dst[(p * 64 + rl) * 2 + 1] =
                    make_float4(pf[p][2], pf[p][2], pf[p][3], pf[p][3]);
            }
        } else {
            const int cl = r;
            // HMMA B: fp16 hi only, stride 48.
            #pragma unroll
            for (int g = 0; g < 2; g++) {
                __align__(16) __half v[16];
                #pragma unroll
                for (int a = 0; a < 4; a++)
                    #pragma unroll
                    for (int b = 0; b < 4; b++)
                        v[a*4+b] = __float2half_rn(pf[2*g][a] * pf[2*g+1][b]);
                uint4* dst = (uint4*)(sm + SM_BH + g * 6144 + cl * 48);
                dst[0] = ((const uint4*)v)[0];
                dst[1] = ((const uint4*)v)[1];
            }
            // FFMA B: pair-interleaved fp32 {f(c0),f(c1)}.
            const int pc = cl >> 1, hf = cl & 1;
            float* bf = (float*)(sm + SM_BF);
            #pragma unroll
            for (int p = 0; p < 4; p++)
                #pragma unroll
                for (int fg = 0; fg < 2; fg++) {
                    float* e = bf + ((p * 2 + fg) * 64 + pc) * 4;
                    e[hf]     = pf[p][2*fg];
                    e[2 + hf] = pf[p][2*fg + 1];
                }
        }
    }
    __syncthreads();

    if (wid < 4) {
        // ---------------- HMMA path: rows [0,64), warp tile 32x64 ----------
        const int wr = wid & 1, wc = wid >> 1;
        uint32_t af[2][2][2][4];
        {
            const uint32_t aoff =
                (uint32_t)(wr * 32 + (lane & 15)) * 80 + (lane >> 4) * 16;
            #pragma unroll
            for (int g = 0; g < 2; g++)
                #pragma unroll
                for (int mt = 0; mt < 2; mt++)
                    #pragma unroll
                    for (int hl = 0; hl < 2; hl++)
                        ldm_x4(af[g][mt][hl],
                               sb + SM_AH + g * 5120 + aoff + mt * 16 * 80 + hl * 32);
        }
        const uint32_t boff =
            (uint32_t)(wc * 64 + (lane & 7) + ((lane >> 4) << 3)) * 48 +
            ((lane >> 3) & 1) * 16;
        const uint32_t bA0 = sb + SM_BH + boff;
        const uint32_t bA1 = sb + SM_BH + 6144 + boff;

        const int colb = col0 + wc * 64 + (lane & 3) * 2;
        const size_t rbase = (size_t)(row0 + wr * 32 + (lane >> 2));

        #pragma unroll
        for (int np = 0; np < 4; np++) {
            const uint32_t bo = np * 16 * 48;
            uint32_t b0[4], b1[4];
            ldm_x4(b0, bA0 + bo);
            ldm_x4(b1, bA1 + bo);

            float acc[2][2][2][4] = {};
            #pragma unroll
            for (int mt = 0; mt < 2; mt++)
                #pragma unroll
                for (int nt = 0; nt < 2; nt++) {
                    mma16816(acc[0][mt][nt], af[0][mt][0], b0[2*nt], b0[2*nt+1]);
                    mma16816(acc[1][mt][nt], af[1][mt][0], b1[2*nt], b1[2*nt+1]);
                }
            #pragma unroll
            for (int mt = 0; mt < 2; mt++)
                #pragma unroll
                for (int nt = 0; nt < 2; nt++) {
                    mma16816(acc[0][mt][nt], af[0][mt][1], b0[2*nt], b0[2*nt+1]);
                    mma16816(acc[1][mt][nt], af[1][mt][1], b1[2*nt], b1[2*nt+1]);
                }
            #pragma unroll
            for (int mt = 0; mt < 2; mt++)
                #pragma unroll
                for (int nt = 0; nt < 2; nt++) {
                    size_t rm = rbase + mt * 16;
                    int cc = colb + np * 16 + nt * 8;
                    float2 v;
                    v.x = fabsf(acc[0][mt][nt][0] * acc[1][mt][nt][0]);
                    v.y = fabsf(acc[0][mt][nt][1] * acc[1][mt][nt][1]);
                    *(float2*)(out + rm * C + cc) = v;
                    v.x = fabsf(acc[0][mt][nt][2] * acc[1][mt][nt][2]);
                    v.y = fabsf(acc[0][mt][nt][3] * acc[1][mt][nt][3]);
                    *(float2*)(out + (rm + 8) * C + cc) = v;
                }
        }
    } else {
        // ---------------- FFMA path: rows [64,128), thread tile 8x8 --------
        const int t = tid - 128;            // 0..127
        const int ty = t >> 4, tx = t & 15;
        const int rbl = ty * 8;             // local row base in [0,64)
        const float4* sAf = (const float4*)(sm + SM_AF);
        const float4* sBf = (const float4*)(sm + SM_BF);

        unsigned long long acc[8][4];
        #pragma unroll
        for (int p = 0; p < 4; p++) {
            unsigned long long b[4][4];
            #pragma unroll
            for (int fg = 0; fg < 2; fg++)
                #pragma unroll
                for (int cp = 0; cp < 4; cp++) {
                    F4U v; v.f = sBf[(p * 2 + fg) * 64 + tx + 16 * cp];
                    b[2*fg + 0][cp] = v.u[0];
                    b[2*fg + 1][cp] = v.u[1];
                }
            #pragma unroll
            for (int r = 0; r < 8; r++) {
                F4U a01, a23;
                a01.f = sAf[(p * 64 + rbl + r) * 2 + 0];
                a23.f = sAf[(p * 64 + rbl + r) * 2 + 1];
                #pragma unroll
                for (int cp = 0; cp < 4; cp++) {
                    unsigned long long tv;
                    asm("mul.rn.f32x2 %0, %1, %2;"     : "=l"(tv) : "l"(a01.u[0]), "l"(b[0][cp]));
                    asm("fma.rn.f32x2 %0, %1, %2, %3;" : "=l"(tv) : "l"(a01.u[1]), "l"(b[1][cp]), "l"(tv));
                    asm("fma.rn.f32x2 %0, %1, %2, %3;" : "=l"(tv) : "l"(a23.u[0]), "l"(b[2][cp]), "l"(tv));
                    asm("fma.rn.f32x2 %0, %1, %2, %3;" : "=l"(tv) : "l"(a23.u[1]), "l"(b[3][cp]), "l"(tv));
                    if (p == 0) acc[r][cp] = tv;
                    else
                        asm("mul.rn.f32x2 %0, %1, %2;"
                            : "=l"(acc[r][cp]) : "l"(acc[r][cp]), "l"(tv));
                }
            }
        }
        #pragma unroll
        for (int r = 0; r < 8; r++) {
            float* orow = out + (size_t)(row0 + 64 + rbl + r) * C + col0 + 2 * tx;
            #pragma unroll
            for (int cp = 0; cp < 4; cp++) {
                unsigned long long v = acc[r][cp] & 0x7FFFFFFF7FFFFFFFull;
                *(unsigned long long*)(orow + 32 * cp) = v;
            }
        }
    }
}

extern "C" void kernel_launch(void* const* d_in, const int* in_sizes, int n_in,
                              void* d_out, int out_size) {
    const float* x = (const float*)d_in[0];
    const float* c = (const float*)d_in[1];
    float* out = (float*)d_out;

    int B = in_sizes[0] / 8;   // 8192
    int C = in_sizes[1] / 8;   // 2048

    static int configured = 0;
    if (!configured) {
        cudaFuncSetAttribute(qk_split, cudaFuncAttributeMaxDynamicSharedMemorySize, SM_TOT);
        configured = 1;
    }

    dim3 grid(C / 128, B / 128);
    qk_split<<<grid, 256, SM_TOT>>>(x, c, out, C);
}

// round 11
// speedup vs baseline: 1.1878x; 1.0977x over previous
#include <cuda_runtime.h>
#include <cuda_fp16.h>
#include <cstdint>
#include <math.h>

// Persistent-panel kernel. Each CTA: 128 rows x 512 cols (4 tiles of 128).
// A features + a-frags computed once; B tiles double-buffered and software-
// pipelined (LDG for tile t+1 issued before tile t's MMAs; features computed
// after). Math identical to R8: A fp16 hi+lo (exact split) x B fp16 hi.
#define SM_A0 0            // A g0: 128 x 80B = 10240
#define SM_A1 10240        // A g1
#define SM_B  20480        // B: 2 buffers x (2 groups x 128 x 48B = 12288)
#define SM_TOT 45056

__device__ __forceinline__ uint32_t smem_u32(const void* p) {
    uint32_t a;
    asm("{ .reg .u64 t; cvta.to.shared.u64 t, %1; cvt.u32.u64 %0, t; }" : "=r"(a) : "l"(p));
    return a;
}
__device__ __forceinline__ void ldm_x4(uint32_t* r, uint32_t addr) {
    asm volatile("ldmatrix.sync.aligned.m8n8.x4.shared.b16 {%0,%1,%2,%3}, [%4];"
                 : "=r"(r[0]), "=r"(r[1]), "=r"(r[2]), "=r"(r[3]) : "r"(addr));
}
__device__ __forceinline__ void mma16816(float* d, const uint32_t* a,
                                         uint32_t b0, uint32_t b1) {
    asm volatile(
        "mma.sync.aligned.m16n8k16.row.col.f32.f16.f16.f32 "
        "{%0,%1,%2,%3}, {%4,%5,%6,%7}, {%8,%9}, {%0,%1,%2,%3};"
        : "+f"(d[0]), "+f"(d[1]), "+f"(d[2]), "+f"(d[3])
        : "r"(a[0]), "r"(a[1]), "r"(a[2]), "r"(a[3]), "r"(b0), "r"(b1));
}

// B features for one column, one 4-wire group: 16 fp16 (hi only) -> STS.
__device__ __forceinline__ void b_feats(float4 cv4, unsigned char* sm,
                                        uint32_t dst_off) {
    float cw[4], sw[4];
    sincosf(0.5f * cv4.x, &sw[0], &cw[0]);
    sincosf(0.5f * cv4.y, &sw[1], &cw[1]);
    sincosf(0.5f * cv4.z, &sw[2], &cw[2]);
    sincosf(0.5f * cv4.w, &sw[3], &cw[3]);
    float pa[4] = {cw[0]*cw[1], cw[0]*sw[1], sw[0]*cw[1], sw[0]*sw[1]};
    float pb[4] = {cw[2]*cw[3], cw[2]*sw[3], sw[2]*cw[3], sw[2]*sw[3]};
    __align__(16) __half v[16];
    #pragma unroll
    for (int a = 0; a < 4; a++)
        #pragma unroll
        for (int b = 0; b < 4; b++)
            v[a*4+b] = __float2half_rn(pa[a] * pb[b]);
    uint4* dst = (uint4*)(sm + dst_off);
    dst[0] = ((const uint4*)v)[0];
    dst[1] = ((const uint4*)v)[1];
}

__global__ void __launch_bounds__(256, 2)
qk_panel(const float* __restrict__ x, const float* __restrict__ c,
         float* __restrict__ out, int C) {
    extern __shared__ __align__(16) unsigned char sm[];
    const int tid = threadIdx.x, wid = tid >> 5, lane = tid & 31;
    const int row0 = blockIdx.y * 128, col0 = blockIdx.x * 512;
    const uint32_t sb = smem_u32(sm);

    const int bcol = tid & 127;         // B column owned by this thread
    const int bgrp = tid >> 7;          // group (0: wires 0-3, 1: wires 4-7)

    // ---------------- One-time prologue ----------------
    // A features: tids 0-127 -> one row each, both groups, fp16 hi|lo.
    if (tid < 128) {
        const float* src = x + (size_t)(row0 + tid) * 8;
        float cv[8], sv[8];
        #pragma unroll
        for (int j = 0; j < 8; j++) sincosf(0.5f * src[j], &sv[j], &cv[j]);
        float pf[4][4];
        #pragma unroll
        for (int p = 0; p < 4; p++) {
            pf[p][0] = cv[2*p] * cv[2*p+1];
            pf[p][1] = cv[2*p] * sv[2*p+1];
            pf[p][2] = sv[2*p] * cv[2*p+1];
            pf[p][3] = sv[2*p] * sv[2*p+1];
        }
        #pragma unroll
        for (int g = 0; g < 2; g++) {
            __align__(16) __half v[32];
            #pragma unroll
            for (int a = 0; a < 4; a++)
                #pragma unroll
                for (int b = 0; b < 4; b++) {
                    float f = pf[2*g][a] * pf[2*g+1][b];
                    __half hi = __float2half_rn(f);
                    v[a*4+b]      = hi;
                    v[16 + a*4+b] = __float2half_rn(f - __half2float(hi));
                }
            uint4* dst = (uint4*)(sm + (g ? SM_A1 : SM_A0) + tid * 80);
            #pragma unroll
            for (int j = 0; j < 4; j++) dst[j] = ((const uint4*)v)[j];
        }
    }
    // B features tile 0: every thread does one (col, group).
    {
        float4 cv4 = *(const float4*)(c + (size_t)(col0 + bcol) * 8 + bgrp * 4);
        b_feats(cv4, sm, SM_B + bgrp * 6144 + bcol * 48);
    }
    __syncthreads();

    // ---------------- Persistent per-warp state ----------------
    const int wr = wid & 3;        // 4 row groups of 32
    const int wc = wid >> 2;       // 2 col groups of 64

    uint32_t af[2][2][2][4];       // a-frags persist across all 4 tiles
    {
        const uint32_t aoff =
            (uint32_t)(wr * 32 + (lane & 15)) * 80 + (lane >> 4) * 16;
        #pragma unroll
        for (int mt = 0; mt < 2; mt++)
            #pragma unroll
            for (int hl = 0; hl < 2; hl++) {
                ldm_x4(af[0][mt][hl], sb + SM_A0 + aoff + mt * 16 * 80 + hl * 32);
                ldm_x4(af[1][mt][hl], sb + SM_A1 + aoff + mt * 16 * 80 + hl * 32);
            }
    }
    const uint32_t boff =
        (uint32_t)(wc * 64 + (lane & 7) + ((lane >> 4) << 3)) * 48 +
        ((lane >> 3) & 1) * 16;

    const int colw = wc * 64 + (lane & 3) * 2;
    const size_t rbase = (size_t)(row0 + wr * 32 + (lane >> 2));

    // ---------------- Tile loop (4 tiles, double-buffered B) ----------------
    #pragma unroll
    for (int t = 0; t < 4; t++) {
        if (t > 0) __syncthreads();   // B(t) features ready; buffer (t+1)&1 free

        // Preload next tile's c values (latency hidden behind MMAs).
        float4 cnext;
        if (t < 3)
            cnext = *(const float4*)(c + (size_t)(col0 + (t+1) * 128 + bcol) * 8 + bgrp * 4);

        const uint32_t bbase = sb + SM_B + (uint32_t)(t & 1) * 12288 + boff;

        #pragma unroll
        for (int np = 0; np < 4; np++) {
            const uint32_t bo = np * 16 * 48;
            uint32_t b0[4], b1[4];
            ldm_x4(b0, bbase + bo);
            ldm_x4(b1, bbase + 6144 + bo);

            float acc[2][2][2][4] = {};   // [g][mt][nt][4]
            #pragma unroll
            for (int mt = 0; mt < 2; mt++)
                #pragma unroll
                for (int nt = 0; nt < 2; nt++) {
                    mma16816(acc[0][mt][nt], af[0][mt][0], b0[2*nt], b0[2*nt+1]);
                    mma16816(acc[1][mt][nt], af[1][mt][0], b1[2*nt], b1[2*nt+1]);
                }
            #pragma unroll
            for (int mt = 0; mt < 2; mt++)
                #pragma unroll
                for (int nt = 0; nt < 2; nt++) {
                    mma16816(acc[0][mt][nt], af[0][mt][1], b0[2*nt], b0[2*nt+1]);
                    mma16816(acc[1][mt][nt], af[1][mt][1], b1[2*nt], b1[2*nt+1]);
                }

            #pragma unroll
            for (int mt = 0; mt < 2; mt++)
                #pragma unroll
                for (int nt = 0; nt < 2; nt++) {
                    size_t rm = rbase + mt * 16;
                    int cc = col0 + t * 128 + colw + np * 16 + nt * 8;
                    float2 v;
                    v.x = fabsf(acc[0][mt][nt][0] * acc[1][mt][nt][0]);
                    v.y = fabsf(acc[0][mt][nt][1] * acc[1][mt][nt][1]);
                    *(float2*)(out + rm * C + cc) = v;
                    v.x = fabsf(acc[0][mt][nt][2] * acc[1][mt][nt][2]);
                    v.y = fabsf(acc[0][mt][nt][3] * acc[1][mt][nt][3]);
                    *(float2*)(out + (rm + 8) * C + cc) = v;
                }
        }

        // Compute next tile's B features into the other buffer.
        if (t < 3)
            b_feats(cnext, sm, SM_B + (uint32_t)((t + 1) & 1) * 12288 +
                               bgrp * 6144 + bcol * 48);
    }
}

extern "C" void kernel_launch(void* const* d_in, const int* in_sizes, int n_in,
                              void* d_out, int out_size) {
    const float* x = (const float*)d_in[0];
    const float* c = (const float*)d_in[1];
    float* out = (float*)d_out;

    int B = in_sizes[0] / 8;   // 8192
    int C = in_sizes[1] / 8;   // 2048

    static int configured = 0;
    if (!configured) {
        cudaFuncSetAttribute(qk_panel, cudaFuncAttributeMaxDynamicSharedMemorySize, SM_TOT);
        configured = 1;
    }

    dim3 grid(C / 512, B / 128);   // (4, 64) = 256 CTAs ≈ 1 wave @ 2 CTAs/SM
    qk_panel<<<grid, 256, SM_TOT>>>(x, c, out, C);
}

// round 12
// speedup vs baseline: 1.1951x; 1.0061x over previous
#include <cuda_runtime.h>
#include <cuda_fp16.h>
#include <cstdint>
#include <math.h>

// Barrier-free mainloop design.
// Pre-kernel: B features (fp16 hi) written in m16n8k16 B-fragment order ->
//   the main loop loads fragments with ONE coalesced LDG.128 per group per
//   16-col step. No smem, no ldmatrix, no __syncthreads for B.
// Main kernel: A features (fp16 hi+lo exact split) built once per CTA in
//   smem, a-frags loaded once via ldmatrix, then a pure streaming loop:
//   prefetch next b-frags -> 16 MMA -> product epilogue -> STG.
// dot = ah.bh + al.bh = a.bh (B-rounding only, rel_err ~2.8e-4, budget 1e-3).

// B-fragment array: [ct=col/16][g] x 32 lanes x 4 uint32 (8 halves).
//   reg r=nt*2+(k>=8), lane L: col = ct*16 + nt*8 + L/4, k = 2*(L%4)+(r&1? wrong..)
//   (exact mapping in qk_bpre below; matches ldmatrix.x4 layout used before.)
__device__ __align__(16) __half gBf[128 * 2 * 32 * 8];   // 128 KB

__device__ __forceinline__ uint32_t smem_u32(const void* p) {
    uint32_t a;
    asm("{ .reg .u64 t; cvta.to.shared.u64 t, %1; cvt.u32.u64 %0, t; }" : "=r"(a) : "l"(p));
    return a;
}
__device__ __forceinline__ void ldm_x4(uint32_t* r, uint32_t addr) {
    asm volatile("ldmatrix.sync.aligned.m8n8.x4.shared.b16 {%0,%1,%2,%3}, [%4];"
                 : "=r"(r[0]), "=r"(r[1]), "=r"(r[2]), "=r"(r[3]) : "r"(addr));
}
__device__ __forceinline__ void mma16816(float* d, const uint32_t* a,
                                         uint32_t b0, uint32_t b1) {
    asm volatile(
        "mma.sync.aligned.m16n8k16.row.col.f32.f16.f16.f32 "
        "{%0,%1,%2,%3}, {%4,%5,%6,%7}, {%8,%9}, {%0,%1,%2,%3};"
        : "+f"(d[0]), "+f"(d[1]), "+f"(d[2]), "+f"(d[3])
        : "r"(a[0]), "r"(a[1]), "r"(a[2]), "r"(a[3]), "r"(b0), "r"(b1));
}

// ---------------- Kernel 1: B-fragment precompute ----------------
__global__ void qk_bpre(const float* __restrict__ c, int C) {
    int idx = blockIdx.x * blockDim.x + threadIdx.x;
    if (idx >= 2 * C) return;
    int col = idx & (C - 1);       // C = 2048 (power of two)
    int g   = idx >> 11;

    float4 cv4 = *(const float4*)(c + (size_t)col * 8 + g * 4);
    float cw[4], sw[4];
    sincosf(0.5f * cv4.x, &sw[0], &cw[0]);
    sincosf(0.5f * cv4.y, &sw[1], &cw[1]);
    sincosf(0.5f * cv4.z, &sw[2], &cw[2]);
    sincosf(0.5f * cv4.w, &sw[3], &cw[3]);
    float pa[4] = {cw[0]*cw[1], cw[0]*sw[1], sw[0]*cw[1], sw[0]*sw[1]};
    float pb[4] = {cw[2]*cw[3], cw[2]*sw[3], sw[2]*cw[3], sw[2]*sw[3]};

    int ct = col >> 4, w = col & 15;
    int nt = w >> 3, nrow = w & 7;
    __half* base = gBf + ((size_t)(ct * 2 + g) * 32) * 8;

    #pragma unroll
    for (int a = 0; a < 4; a++)
        #pragma unroll
        for (int b = 0; b < 4; b++) {
            int k = a * 4 + b;                       // feature index 0..15
            __half hv = __float2half_rn(pa[a] * pb[b]);
            int L = nrow * 4 + ((k & 7) >> 1);       // lane
            int r = nt * 2 + (k >> 3);               // reg 0..3
            base[L * 8 + r * 2 + (k & 1)] = hv;
        }
}

// ---------------- Kernel 2: main, barrier-free mainloop ----------------
// CTA: 128 rows x 512 cols. 8 warps: 4 row groups (32r) x 2 col groups (256c).
// Warp loop: 16 steps of 16 cols; per step 2 LDG.128 + 16 MMA + stores.
__global__ void __launch_bounds__(256, 2)
qk_main(const float* __restrict__ x, float* __restrict__ out, int C) {
    __shared__ __align__(16) unsigned char smA[20480];   // 2 groups x 128 x 80B
    const int tid = threadIdx.x, wid = tid >> 5, lane = tid & 31;
    const int row0 = blockIdx.y * 128, col0 = blockIdx.x * 512;
    const uint32_t sb = smem_u32(smA);

    // ---- A prologue (once per CTA): fp16 hi|lo features, stride 80 ----
    if (tid < 128) {
        const float* src = x + (size_t)(row0 + tid) * 8;
        float cv[8], sv[8];
        #pragma unroll
        for (int j = 0; j < 8; j++) sincosf(0.5f * src[j], &sv[j], &cv[j]);
        float pf[4][4];
        #pragma unroll
        for (int p = 0; p < 4; p++) {
            pf[p][0] = cv[2*p] * cv[2*p+1];
            pf[p][1] = cv[2*p] * sv[2*p+1];
            pf[p][2] = sv[2*p] * cv[2*p+1];
            pf[p][3] = sv[2*p] * sv[2*p+1];
        }
        #pragma unroll
        for (int g = 0; g < 2; g++) {
            __align__(16) __half v[32];
            #pragma unroll
            for (int a = 0; a < 4; a++)
                #pragma unroll
                for (int b = 0; b < 4; b++) {
                    float f = pf[2*g][a] * pf[2*g+1][b];
                    __half hi = __float2half_rn(f);
                    v[a*4+b]      = hi;
                    v[16 + a*4+b] = __float2half_rn(f - __half2float(hi));
                }
            uint4* dst = (uint4*)(smA + g * 10240 + tid * 80);
            #pragma unroll
            for (int j = 0; j < 4; j++) dst[j] = ((const uint4*)v)[j];
        }
    }
    __syncthreads();    // the ONLY barrier

    const int wr = wid & 3;       // row group
    const int wc = wid >> 2;      // col group

    // Persistent a-frags: af[g][mt][hl][4], 32 regs.
    uint32_t af[2][2][2][4];
    {
        const uint32_t aoff =
            (uint32_t)(wr * 32 + (lane & 15)) * 80 + (lane >> 4) * 16;
        #pragma unroll
        for (int mt = 0; mt < 2; mt++)
            #pragma unroll
            for (int hl = 0; hl < 2; hl++) {
                ldm_x4(af[0][mt][hl], sb + aoff + mt * 16 * 80 + hl * 32);
                ldm_x4(af[1][mt][hl], sb + 10240 + aoff + mt * 16 * 80 + hl * 32);
            }
    }

    const uint4* bf = (const uint4*)gBf;
    const int ctb = (col0 >> 4) + wc * 16;     // first 16-col step
    const int colw = (lane & 3) * 2;
    const size_t rbase = (size_t)(row0 + wr * 32 + (lane >> 2));

    uint4 cur0 = bf[(ctb * 2 + 0) * 32 + lane];
    uint4 cur1 = bf[(ctb * 2 + 1) * 32 + lane];

    #pragma unroll 4
    for (int i = 0; i < 16; i++) {
        uint4 nb0, nb1;
        if (i < 15) {
            nb0 = bf[((ctb + i + 1) * 2 + 0) * 32 + lane];
            nb1 = bf[((ctb + i + 1) * 2 + 1) * 32 + lane];
        }

        float acc[2][2][2][4] = {};   // [g][mt][nt][4]
        // k-step 1: ah . bh  (8 independent MMAs)
        #pragma unroll
        for (int mt = 0; mt < 2; mt++) {
            mma16816(acc[0][mt][0], af[0][mt][0], cur0.x, cur0.y);
            mma16816(acc[1][mt][0], af[1][mt][0], cur1.x, cur1.y);
            mma16816(acc[0][mt][1], af[0][mt][0], cur0.z, cur0.w);
            mma16816(acc[1][mt][1], af[1][mt][0], cur1.z, cur1.w);
        }
        // k-step 2: al . bh
        #pragma unroll
        for (int mt = 0; mt < 2; mt++) {
            mma16816(acc[0][mt][0], af[0][mt][1], cur0.x, cur0.y);
            mma16816(acc[1][mt][0], af[1][mt][1], cur1.x, cur1.y);
            mma16816(acc[0][mt][1], af[0][mt][1], cur0.z, cur0.w);
            mma16816(acc[1][mt][1], af[1][mt][1], cur1.z, cur1.w);
        }

        // Epilogue: out = |D1 * D2|
        const int cbase = col0 + wc * 256 + i * 16 + colw;
        #pragma unroll
        for (int mt = 0; mt < 2; mt++)
            #pragma unroll
            for (int nt = 0; nt < 2; nt++) {
                size_t rm = rbase + mt * 16;
                int cc = cbase + nt * 8;
                float2 v;
                v.x = fabsf(acc[0][mt][nt][0] * acc[1][mt][nt][0]);
                v.y = fabsf(acc[0][mt][nt][1] * acc[1][mt][nt][1]);
                *(float2*)(out + rm * C + cc) = v;
                v.x = fabsf(acc[0][mt][nt][2] * acc[1][mt][nt][2]);
                v.y = fabsf(acc[0][mt][nt][3] * acc[1][mt][nt][3]);
                *(float2*)(out + (rm + 8) * C + cc) = v;
            }

        cur0 = nb0; cur1 = nb1;
    }
}

extern "C" void kernel_launch(void* const* d_in, const int* in_sizes, int n_in,
                              void* d_out, int out_size) {
    const float* x = (const float*)d_in[0];
    const float* c = (const float*)d_in[1];
    float* out = (float*)d_out;

    int B = in_sizes[0] / 8;   // 8192
    int C = in_sizes[1] / 8;   // 2048

    qk_bpre<<<(2 * C + 255) / 256, 256>>>(c, C);

    dim3 grid(C / 512, B / 128);   // (4, 64) = 256 CTAs
    qk_main<<<grid, 256>>>(x, out, C);
}

// round 14
// speedup vs baseline: 1.2988x; 1.0868x over previous
#include <cuda_runtime.h>
#include <cuda_fp16.h>
#include <cstdint>
#include <math.h>

// Single fused kernel, barrier-free mainloop (R12 math, smem-resident B-frags).
// CTA: 128 rows x 512 cols, 8 warps = 4 row groups (32r) x 2 col groups (256c).
// Prologue (one barrier total):
//   tid<128: A features fp16 hi|lo (exact fp32 split), stride 80.
//   all tids: 4 (col,g) units -> B features fp16 hi, packed DIRECTLY in
//             m16n8k16 B-fragment order in smem (4 STS.64 per unit).
// Mainloop per warp, per 16-col step: 2 LDS.128 (b-frags) + 16 MMA + stores.
// dot = ah.bh + al.bh = a.bh  (B-rounding only; rel_err ~2.8e-4, budget 1e-3).

#define SM_A  0            // 2 groups x 128 rows x 80B = 20480
#define SM_B  20480        // 32 ct x 2 g x 32 lanes x 16B = 32768
#define SM_TOT 53248       // dynamic smem (>48KB static limit)

__device__ __forceinline__ uint32_t smem_u32(const void* p) {
    uint32_t a;
    asm("{ .reg .u64 t; cvta.to.shared.u64 t, %1; cvt.u32.u64 %0, t; }" : "=r"(a) : "l"(p));
    return a;
}
__device__ __forceinline__ void ldm_x4(uint32_t* r, uint32_t addr) {
    asm volatile("ldmatrix.sync.aligned.m8n8.x4.shared.b16 {%0,%1,%2,%3}, [%4];"
                 : "=r"(r[0]), "=r"(r[1]), "=r"(r[2]), "=r"(r[3]) : "r"(addr));
}
__device__ __forceinline__ void mma16816(float* d, const uint32_t* a,
                                         uint32_t b0, uint32_t b1) {
    asm volatile(
        "mma.sync.aligned.m16n8k16.row.col.f32.f16.f16.f32 "
        "{%0,%1,%2,%3}, {%4,%5,%6,%7}, {%8,%9}, {%0,%1,%2,%3};"
        : "+f"(d[0]), "+f"(d[1]), "+f"(d[2]), "+f"(d[3])
        : "r"(a[0]), "r"(a[1]), "r"(a[2]), "r"(a[3]), "r"(b0), "r"(b1));
}
__device__ __forceinline__ unsigned long long pack4h(float f0, float f1,
                                                     float f2, float f3) {
    __half2 lo = __floats2half2_rn(f0, f1);
    __half2 hi = __floats2half2_rn(f2, f3);
    unsigned long long r;
    asm("mov.b64 %0, {%1, %2};" : "=l"(r)
        : "r"(*(unsigned int*)&lo), "r"(*(unsigned int*)&hi));
    return r;
}

__global__ void __launch_bounds__(256, 2)
qk_one(const float* __restrict__ x, const float* __restrict__ c,
       float* __restrict__ out, int C) {
    extern __shared__ __align__(16) unsigned char sm[];
    const int tid = threadIdx.x, wid = tid >> 5, lane = tid & 31;
    const int row0 = blockIdx.y * 128, col0 = blockIdx.x * 512;
    const uint32_t sb = smem_u32(sm);

    // ---------------- Prologue ----------------
    // A features: tids 0-127, one row each.
    if (tid < 128) {
        const float* src = x + (size_t)(row0 + tid) * 8;
        float cv[8], sv[8];
        #pragma unroll
        for (int j = 0; j < 8; j++) sincosf(0.5f * src[j], &sv[j], &cv[j]);
        float pf[4][4];
        #pragma unroll
        for (int p = 0; p < 4; p++) {
            pf[p][0] = cv[2*p] * cv[2*p+1];
            pf[p][1] = cv[2*p] * sv[2*p+1];
            pf[p][2] = sv[2*p] * cv[2*p+1];
            pf[p][3] = sv[2*p] * sv[2*p+1];
        }
        #pragma unroll
        for (int g = 0; g < 2; g++) {
            __align__(16) __half v[32];
            #pragma unroll
            for (int a = 0; a < 4; a++)
                #pragma unroll
                for (int b = 0; b < 4; b++) {
                    float f = pf[2*g][a] * pf[2*g+1][b];
                    __half hi = __float2half_rn(f);
                    v[a*4+b]      = hi;
                    v[16 + a*4+b] = __float2half_rn(f - __half2float(hi));
                }
            uint4* dst = (uint4*)(sm + SM_A + g * 10240 + tid * 80);
            #pragma unroll
            for (int j = 0; j < 4; j++) dst[j] = ((const uint4*)v)[j];
        }
    }

    // B fragments: 1024 (col,g) units, 4 per thread, written in fragment order.
    #pragma unroll
    for (int p = 0; p < 4; p++) {
        const int u = tid + p * 256;        // 0..1023
        const int col = u & 511, g = u >> 9;
        float4 cv4 = *(const float4*)(c + (size_t)(col0 + col) * 8 + g * 4);
        float cw[4], sw[4];
        sincosf(0.5f * cv4.x, &sw[0], &cw[0]);
        sincosf(0.5f * cv4.y, &sw[1], &cw[1]);
        sincosf(0.5f * cv4.z, &sw[2], &cw[2]);
        sincosf(0.5f * cv4.w, &sw[3], &cw[3]);
        float pa[4] = {cw[0]*cw[1], cw[0]*sw[1], sw[0]*cw[1], sw[0]*sw[1]};
        float pb[4] = {cw[2]*cw[3], cw[2]*sw[3], sw[2]*cw[3], sw[2]*sw[3]};

        const int ct = col >> 4, w = col & 15;
        const int nt = w >> 3, nrow = w & 7;
        unsigned char* base = sm + SM_B + ((ct * 2 + g) * 32) * 16 + nt * 8;
        #pragma unroll
        for (int j = 0; j < 4; j++) {
            // halves {f[2j], f[2j+1], f[2j+8], f[2j+9]},  f[k]=pa[k>>2]*pb[k&3]
            int k0 = 2 * j, k1 = 2 * j + 1, k8 = 2 * j + 8, k9 = 2 * j + 9;
            unsigned long long v = pack4h(
                pa[k0 >> 2] * pb[k0 & 3], pa[k1 >> 2] * pb[k1 & 3],
                pa[k8 >> 2] * pb[k8 & 3], pa[k9 >> 2] * pb[k9 & 3]);
            *(unsigned long long*)(base + (nrow * 4 + j) * 16) = v;
        }
    }
    __syncthreads();    // the ONLY barrier

    // ---------------- Persistent a-frags ----------------
    const int wr = wid & 3;       // row group
    const int wc = wid >> 2;      // col group
    uint32_t af[2][2][2][4];      // [g][mt][hl][4]
    {
        const uint32_t aoff =
            (uint32_t)(wr * 32 + (lane & 15)) * 80 + (lane >> 4) * 16;
        #pragma unroll
        for (int mt = 0; mt < 2; mt++)
            #pragma unroll
            for (int hl = 0; hl < 2; hl++) {
                ldm_x4(af[0][mt][hl], sb + SM_A + aoff + mt * 16 * 80 + hl * 32);
                ldm_x4(af[1][mt][hl], sb + SM_A + 10240 + aoff + mt * 16 * 80 + hl * 32);
            }
    }

    const int colw = (lane & 3) * 2;
    const size_t rbase = (size_t)(row0 + wr * 32 + (lane >> 2));
    const uint32_t bbase = sb + SM_B + lane * 16;

    #pragma unroll 4
    for (int i = 0; i < 16; i++) {
        const int ct = wc * 16 + i;           // CTA-local 16-col step
        uint4 cur0, cur1;
        {
            const uint32_t a0 = bbase + (uint32_t)(ct * 2 + 0) * 512;
            const uint32_t a1 = bbase + (uint32_t)(ct * 2 + 1) * 512;
            asm volatile("ld.shared.v4.b32 {%0,%1,%2,%3}, [%4];"
                         : "=r"(cur0.x), "=r"(cur0.y), "=r"(cur0.z), "=r"(cur0.w)
                         : "r"(a0));
            asm volatile("ld.shared.v4.b32 {%0,%1,%2,%3}, [%4];"
                         : "=r"(cur1.x), "=r"(cur1.y), "=r"(cur1.z), "=r"(cur1.w)
                         : "r"(a1));
        }

        float acc[2][2][2][4] = {};   // [g][mt][nt][4]
        // k-step 1: ah . bh  (8 independent MMAs)
        #pragma unroll
        for (int mt = 0; mt < 2; mt++) {
            mma16816(acc[0][mt][0], af[0][mt][0], cur0.x, cur0.y);
            mma16816(acc[1][mt][0], af[1][mt][0], cur1.x, cur1.y);
            mma16816(acc[0][mt][1], af[0][mt][0], cur0.z, cur0.w);
            mma16816(acc[1][mt][1], af[1][mt][0], cur1.z, cur1.w);
        }
        // k-step 2: al . bh
        #pragma unroll
        for (int mt = 0; mt < 2; mt++) {
            mma16816(acc[0][mt][0], af[0][mt][1], cur0.x, cur0.y);
            mma16816(acc[1][mt][0], af[1][mt][1], cur1.x, cur1.y);
            mma16816(acc[0][mt][1], af[0][mt][1], cur0.z, cur0.w);
            mma16816(acc[1][mt][1], af[1][mt][1], cur1.z, cur1.w);
        }

        // Epilogue: out = |D1 * D2|
        const int cbase = col0 + ct * 16 + colw;
        #pragma unroll
        for (int mt = 0; mt < 2; mt++)
            #pragma unroll
            for (int nt = 0; nt < 2; nt++) {
                size_t rm = rbase + mt * 16;
                int cc = cbase + nt * 8;
                float2 v;
                v.x = fabsf(acc[0][mt][nt][0] * acc[1][mt][nt][0]);
                v.y = fabsf(acc[0][mt][nt][1] * acc[1][mt][nt][1]);
                *(float2*)(out + rm * C + cc) = v;
                v.x = fabsf(acc[0][mt][nt][2] * acc[1][mt][nt][2]);
                v.y = fabsf(acc[0][mt][nt][3] * acc[1][mt][nt][3]);
                *(float2*)(out + (rm + 8) * C + cc) = v;
            }
    }
}

extern "C" void kernel_launch(void* const* d_in, const int* in_sizes, int n_in,
                              void* d_out, int out_size) {
    const float* x = (const float*)d_in[0];
    const float* c = (const float*)d_in[1];
    float* out = (float*)d_out;

    int B = in_sizes[0] / 8;   // 8192
    int C = in_sizes[1] / 8;   // 2048

    static int configured = 0;
    if (!configured) {
        cudaFuncSetAttribute(qk_one, cudaFuncAttributeMaxDynamicSharedMemorySize, SM_TOT);
        configured = 1;
    }

    dim3 grid(C / 512, B / 128);   // (4, 64) = 256 CTAs
    qk_one<<<grid, 256, SM_TOT>>>(x, c, out, C);
}